// round 4
// baseline (speedup 1.0000x reference)
#include <cuda_runtime.h>

// ---------------- problem constants ----------------
#define BB   256
#define CC   3
#define HH   224
#define WWD  224
#define RET  32
#define GDIM 9216          // 3 * 3 * 32 * 32
#define HGN  1024
#define HLN  256
#define HOUT 1280          // HG + HL

// ---------------- scratch (device globals; no allocation allowed) ----------
__device__ float g_buf [BB * GDIM];   // foveated glimpse, (B, 9216)
__device__ float h1_buf[BB * HGN];    // relu(g@W1+b1)
__device__ float h2_buf[BB * HLN];    // relu(loc@W2+b2)
__device__ float hl_buf[BB * HOUT];   // relu(h2@W4+b4)

// ---------------- foveation -----------------------------------------------
// g[b, z, c, y, x]:
//   denorm = (loc+1)*0.5*224 ; half = 16<<z ; top/left = trunc(denorm-half)
//   z=0: direct copy
//   z=1: jax bilinear coord = 2i+0.5  -> mean of 2x2 block at (2y, 2x)
//   z=2: jax bilinear coord = 4i+1.5  -> mean of 2x2 block at (4y+1, 4x+1)
__global__ void foveate_kernel(const float* __restrict__ img,
                               const float* __restrict__ loc) {
    int idx = blockIdx.x * blockDim.x + threadIdx.x;
    if (idx >= BB * GDIM) return;
    int b  = idx / GDIM;
    int r  = idx - b * GDIM;
    int z  = r / (CC * RET * RET);
    int r2 = r - z * (CC * RET * RET);
    int c  = r2 / (RET * RET);
    int p  = r2 - c * (RET * RET);
    int y  = p >> 5;
    int x  = p & 31;

    float dr = (loc[b * 2 + 0] + 1.0f) * 0.5f * (float)WWD;
    float dc = (loc[b * 2 + 1] + 1.0f) * 0.5f * (float)WWD;
    int half = 16 << z;
    int top  = (int)(dr - (float)half);   // in-bounds & positive -> trunc == floor
    int left = (int)(dc - (float)half);

    const float* im = img + ((size_t)b * CC + c) * (HH * WWD);
    float v;
    if (z == 0) {
        v = im[(top + y) * WWD + (left + x)];
    } else {
        int off = (z == 2) ? 1 : 0;
        int yy = top  + (y << z) + off;
        int xx = left + (x << z) + off;
        const float* p0 = im + yy * WWD + xx;
        v = 0.25f * (p0[0] + p0[1] + p0[WWD] + p0[WWD + 1]);
    }
    g_buf[idx] = v;
}

// ---------------- location FC (K=2) ---------------------------------------
__global__ void loc_fc_kernel(const float* __restrict__ loc,
                              const float* __restrict__ W2,
                              const float* __restrict__ b2) {
    int b = blockIdx.x;
    int n = threadIdx.x;                 // 0..255
    float l0 = loc[b * 2 + 0];
    float l1 = loc[b * 2 + 1];
    float v = fmaf(l0, W2[n], fmaf(l1, W2[HLN + n], b2[n]));
    h2_buf[b * HLN + n] = fmaxf(v, 0.0f);
}

// ---------------- tiled fp32 GEMM:  C = f(A[MxK] @ W[KxN] + bias) ---------
// BM=32, BN=64, BK=32, 128 threads, 4x4 micro-tile per thread.
// Requires M%32==0, N%64==0, K%32==0 (true for all call sites).
template<bool RELU, bool ADDIN>
__global__ __launch_bounds__(128)
void gemm_kernel(const float* __restrict__ A, const float* __restrict__ W,
                 const float* __restrict__ bias, const float* __restrict__ add,
                 float* __restrict__ C, int M, int N, int K) {
    __shared__ float As[32][33];   // [k][m], padded
    __shared__ float Ws[32][64];   // [k][n]

    const int tid = threadIdx.x;
    const int bm  = blockIdx.y;
    const int bn  = blockIdx.x;
    const int ty  = tid >> 4;      // 0..7  -> 4 rows each
    const int tx  = tid & 15;      // 0..15 -> 4 cols each

    float acc[4][4] = {};

    for (int k0 = 0; k0 < K; k0 += 32) {
        // load A tile (32x32) = 256 float4, 2 per thread, coalesced
        #pragma unroll
        for (int t = 0; t < 2; t++) {
            int i  = t * 128 + tid;
            int ar = i >> 3;
            int ac = (i & 7) << 2;
            float4 v = *(const float4*)(A + (size_t)(bm * 32 + ar) * K + k0 + ac);
            As[ac + 0][ar] = v.x;
            As[ac + 1][ar] = v.y;
            As[ac + 2][ar] = v.z;
            As[ac + 3][ar] = v.w;
        }
        // load W tile (32x64) = 512 float4, 4 per thread, coalesced
        #pragma unroll
        for (int t = 0; t < 4; t++) {
            int i  = t * 128 + tid;
            int wr = i >> 4;
            int wc = (i & 15) << 2;
            *(float4*)(&Ws[wr][wc]) =
                *(const float4*)(W + (size_t)(k0 + wr) * N + bn * 64 + wc);
        }
        __syncthreads();

        #pragma unroll
        for (int kk = 0; kk < 32; kk++) {
            float a0 = As[kk][ty * 4 + 0];
            float a1 = As[kk][ty * 4 + 1];
            float a2 = As[kk][ty * 4 + 2];
            float a3 = As[kk][ty * 4 + 3];
            float4 wq = *(const float4*)(&Ws[kk][tx * 4]);
            acc[0][0] = fmaf(a0, wq.x, acc[0][0]);
            acc[0][1] = fmaf(a0, wq.y, acc[0][1]);
            acc[0][2] = fmaf(a0, wq.z, acc[0][2]);
            acc[0][3] = fmaf(a0, wq.w, acc[0][3]);
            acc[1][0] = fmaf(a1, wq.x, acc[1][0]);
            acc[1][1] = fmaf(a1, wq.y, acc[1][1]);
            acc[1][2] = fmaf(a1, wq.z, acc[1][2]);
            acc[1][3] = fmaf(a1, wq.w, acc[1][3]);
            acc[2][0] = fmaf(a2, wq.x, acc[2][0]);
            acc[2][1] = fmaf(a2, wq.y, acc[2][1]);
            acc[2][2] = fmaf(a2, wq.z, acc[2][2]);
            acc[2][3] = fmaf(a2, wq.w, acc[2][3]);
            acc[3][0] = fmaf(a3, wq.x, acc[3][0]);
            acc[3][1] = fmaf(a3, wq.y, acc[3][1]);
            acc[3][2] = fmaf(a3, wq.z, acc[3][2]);
            acc[3][3] = fmaf(a3, wq.w, acc[3][3]);
        }
        __syncthreads();
    }

    // epilogue: C = [relu](acc + bias) [+ add]
    const int col0 = bn * 64 + tx * 4;
    float4 bv = *(const float4*)(bias + col0);
    #pragma unroll
    for (int i = 0; i < 4; i++) {
        int row = bm * 32 + ty * 4 + i;
        float4 o;
        o.x = acc[i][0] + bv.x;
        o.y = acc[i][1] + bv.y;
        o.z = acc[i][2] + bv.z;
        o.w = acc[i][3] + bv.w;
        if (RELU) {
            o.x = fmaxf(o.x, 0.0f);
            o.y = fmaxf(o.y, 0.0f);
            o.z = fmaxf(o.z, 0.0f);
            o.w = fmaxf(o.w, 0.0f);
        }
        if (ADDIN) {
            float4 av = *(const float4*)(add + (size_t)row * N + col0);
            o.x += av.x; o.y += av.y; o.z += av.z; o.w += av.w;
        }
        *(float4*)(C + (size_t)row * N + col0) = o;
    }
}

// ---------------- launch ----------------------------------------------------
extern "C" void kernel_launch(void* const* d_in, const int* in_sizes, int n_in,
                              void* d_out, int out_size) {
    const float* images    = (const float*)d_in[0];
    const float* locations = (const float*)d_in[1];
    const float* W1        = (const float*)d_in[2];
    const float* b1        = (const float*)d_in[3];
    const float* W2        = (const float*)d_in[4];
    const float* b2        = (const float*)d_in[5];
    const float* W3        = (const float*)d_in[6];
    const float* b3        = (const float*)d_in[7];
    const float* W4        = (const float*)d_in[8];
    const float* b4        = (const float*)d_in[9];
    float* out = (float*)d_out;
    (void)in_sizes; (void)n_in; (void)out_size;

    void *gp, *h1p, *h2p, *hlp;
    cudaGetSymbolAddress(&gp,  g_buf);
    cudaGetSymbolAddress(&h1p, h1_buf);
    cudaGetSymbolAddress(&h2p, h2_buf);
    cudaGetSymbolAddress(&hlp, hl_buf);

    // 1) foveation -> g_buf
    foveate_kernel<<<(BB * GDIM + 255) / 256, 256>>>(images, locations);

    // 2) location FC -> h2_buf
    loc_fc_kernel<<<BB, HLN>>>(locations, W2, b2);

    // 3) hl = relu(h2 @ W4 + b4)            (256 x 1280, K=256)
    gemm_kernel<true, false><<<dim3(HOUT / 64, BB / 32), 128>>>(
        (const float*)h2p, W4, b4, nullptr, (float*)hlp, BB, HOUT, HLN);

    // 4) h1 = relu(g @ W1 + b1)             (256 x 1024, K=9216)  -- dominant
    gemm_kernel<true, false><<<dim3(HGN / 64, BB / 32), 128>>>(
        (const float*)gp, W1, b1, nullptr, (float*)h1p, BB, HGN, GDIM);

    // 5) out = relu(h1 @ W3 + b3) + hl      (== relu(hg + hl), both >= 0)
    gemm_kernel<true, true><<<dim3(HOUT / 64, BB / 32), 128>>>(
        (const float*)h1p, W3, b3, (const float*)hlp, out, BB, HOUT, HGN);
}

// round 5
// speedup vs baseline: 3.2449x; 3.2449x over previous
#include <cuda_runtime.h>

// ---------------- problem constants ----------------
#define BB   256
#define CC   3
#define HH   224
#define WWD  224
#define RET  32
#define GDIM 9216          // 3 * 3 * 32 * 32
#define HGN  1024
#define HLN  256
#define HOUT 1280          // HG + HL

#define S1   8             // split-K for GEMM1 (K=9216 -> 1152/split)
#define S2   4             // split-K for out GEMM (K=1024 -> 256/split)
#define S3   2             // split-K for hl GEMM  (K=256  -> 128/split)

// ---------------- scratch (device globals; no allocation allowed) ----------
__device__ float g_buf [BB * GDIM];          // foveated glimpse (B, 9216)
__device__ float h1_buf[BB * HGN];           // relu(g@W1+b1)
__device__ float h2_buf[BB * HLN];           // relu(loc@W2+b2)
__device__ float part1[S1 * BB * HGN];       // GEMM1 partials
__device__ float part2[S2 * BB * HOUT];      // h1@W3 partials
__device__ float part3[S3 * BB * HOUT];      // h2@W4 partials

// ---------------- packed fp32x2 helpers (sm_103a FFMA2) --------------------
__device__ __forceinline__ void fma2(unsigned long long& d,
                                     unsigned long long a,
                                     unsigned long long b) {
    asm("fma.rn.f32x2 %0, %1, %2, %0;" : "+l"(d) : "l"(a), "l"(b));
}
__device__ __forceinline__ unsigned long long pack_dup(float x) {
    unsigned long long r;
    unsigned xi = __float_as_uint(x);
    asm("mov.b64 %0, {%1, %2};" : "=l"(r) : "r"(xi), "r"(xi));
    return r;
}
__device__ __forceinline__ float2 unpack2(unsigned long long v) {
    unsigned lo, hi;
    asm("mov.b64 {%0, %1}, %2;" : "=r"(lo), "=r"(hi) : "l"(v));
    return make_float2(__uint_as_float(lo), __uint_as_float(hi));
}

// ---------------- foveation -----------------------------------------------
__global__ void foveate_kernel(const float* __restrict__ img,
                               const float* __restrict__ loc) {
    int idx = blockIdx.x * blockDim.x + threadIdx.x;
    if (idx >= BB * GDIM) return;
    int b  = idx / GDIM;
    int r  = idx - b * GDIM;
    int z  = r / (CC * RET * RET);
    int r2 = r - z * (CC * RET * RET);
    int c  = r2 / (RET * RET);
    int p  = r2 - c * (RET * RET);
    int y  = p >> 5;
    int x  = p & 31;

    float dr = (loc[b * 2 + 0] + 1.0f) * 0.5f * (float)WWD;
    float dc = (loc[b * 2 + 1] + 1.0f) * 0.5f * (float)WWD;
    int half = 16 << z;
    int top  = (int)(dr - (float)half);
    int left = (int)(dc - (float)half);

    const float* im = img + ((size_t)b * CC + c) * (HH * WWD);
    float v;
    if (z == 0) {
        v = im[(top + y) * WWD + (left + x)];
    } else {
        int off = (z == 2) ? 1 : 0;
        int yy = top  + (y << z) + off;
        int xx = left + (x << z) + off;
        const float* p0 = im + yy * WWD + xx;
        v = 0.25f * (p0[0] + p0[1] + p0[WWD] + p0[WWD + 1]);
    }
    g_buf[idx] = v;
}

// ---------------- location FC (K=2) ---------------------------------------
__global__ void loc_fc_kernel(const float* __restrict__ loc,
                              const float* __restrict__ W2,
                              const float* __restrict__ b2) {
    int b = blockIdx.x;
    int n = threadIdx.x;
    float l0 = loc[b * 2 + 0];
    float l1 = loc[b * 2 + 1];
    float v = fmaf(l0, W2[n], fmaf(l1, W2[HLN + n], b2[n]));
    h2_buf[b * HLN + n] = fmaxf(v, 0.0f);
}

// ---------------- split-K tiled fp32 GEMM (FFMA2 inner loop) ---------------
// part[z] += A[MxK chunk z] @ W[chunk z x N]
// BM=32, BN=64, BK=32, 128 threads, 4x4 per thread (2 f32x2 pairs wide).
// gridDim = (N/64, M/32, S); Kc = K / S, Kc % 32 == 0.
__global__ __launch_bounds__(128)
void gemm_splitk_kernel(const float* __restrict__ A, const float* __restrict__ W,
                        float* __restrict__ part, int M, int N, int K, int Kc) {
    __shared__ float As[32][36];   // [k][m], stride 36 -> 16B-aligned float4 rows
    __shared__ float Ws[32][64];   // [k][n]

    const int tid = threadIdx.x;
    const int bm  = blockIdx.y;
    const int bn  = blockIdx.x;
    const int sz  = blockIdx.z;
    const int ty  = tid >> 4;      // 0..7  -> 4 rows
    const int tx  = tid & 15;      // 0..15 -> 4 cols (2 pairs)

    const int kbase = sz * Kc;

    unsigned long long acc[4][2];
    #pragma unroll
    for (int i = 0; i < 4; i++) { acc[i][0] = 0ull; acc[i][1] = 0ull; }

    for (int k0 = 0; k0 < Kc; k0 += 32) {
        // A tile (32 rows x 32 k) : 256 float4, 2/thread, coalesced; store transposed
        #pragma unroll
        for (int t = 0; t < 2; t++) {
            int i  = t * 128 + tid;
            int ar = i >> 3;
            int ac = (i & 7) << 2;
            float4 v = *(const float4*)(A + (size_t)(bm * 32 + ar) * K + kbase + k0 + ac);
            As[ac + 0][ar] = v.x;
            As[ac + 1][ar] = v.y;
            As[ac + 2][ar] = v.z;
            As[ac + 3][ar] = v.w;
        }
        // W tile (32 k x 64 n) : 512 float4, 4/thread, coalesced
        #pragma unroll
        for (int t = 0; t < 4; t++) {
            int i  = t * 128 + tid;
            int wr = i >> 4;
            int wc = (i & 15) << 2;
            *(float4*)(&Ws[wr][wc]) =
                *(const float4*)(W + (size_t)(kbase + k0 + wr) * N + bn * 64 + wc);
        }
        __syncthreads();

        #pragma unroll
        for (int kk = 0; kk < 32; kk++) {
            float4 av = *(const float4*)(&As[kk][ty * 4]);       // 16B aligned
            float4 wv = *(const float4*)(&Ws[kk][tx * 4]);
            unsigned long long w01 = ((const unsigned long long*)&wv)[0];
            unsigned long long w23 = ((const unsigned long long*)&wv)[1];
            unsigned long long a0 = pack_dup(av.x);
            unsigned long long a1 = pack_dup(av.y);
            unsigned long long a2 = pack_dup(av.z);
            unsigned long long a3 = pack_dup(av.w);
            fma2(acc[0][0], a0, w01); fma2(acc[0][1], a0, w23);
            fma2(acc[1][0], a1, w01); fma2(acc[1][1], a1, w23);
            fma2(acc[2][0], a2, w01); fma2(acc[2][1], a2, w23);
            fma2(acc[3][0], a3, w01); fma2(acc[3][1], a3, w23);
        }
        __syncthreads();
    }

    // write raw partials: part[sz][row][col]
    float* pout = part + (size_t)sz * M * N;
    const int col0 = bn * 64 + tx * 4;
    #pragma unroll
    for (int i = 0; i < 4; i++) {
        int row = bm * 32 + ty * 4 + i;
        float2 p0 = unpack2(acc[i][0]);
        float2 p1 = unpack2(acc[i][1]);
        float4 o = make_float4(p0.x, p0.y, p1.x, p1.y);
        *(float4*)(pout + (size_t)row * N + col0) = o;
    }
}

// ---------------- reduce 1: h1 = relu(sum_s part1 + b1) --------------------
__global__ void reduce1_kernel(const float* __restrict__ b1) {
    int idx4 = blockIdx.x * blockDim.x + threadIdx.x;        // over (BB*HGN)/4
    if (idx4 >= BB * HGN / 4) return;
    int idx = idx4 * 4;
    int n   = idx % HGN;
    float4 s = *(const float4*)(part1 + idx);
    #pragma unroll
    for (int z = 1; z < S1; z++) {
        float4 v = *(const float4*)(part1 + (size_t)z * BB * HGN + idx);
        s.x += v.x; s.y += v.y; s.z += v.z; s.w += v.w;
    }
    float4 bv = *(const float4*)(b1 + n);
    s.x = fmaxf(s.x + bv.x, 0.0f);
    s.y = fmaxf(s.y + bv.y, 0.0f);
    s.z = fmaxf(s.z + bv.z, 0.0f);
    s.w = fmaxf(s.w + bv.w, 0.0f);
    *(float4*)(h1_buf + idx) = s;
}

// ---------------- final reduce: out = relu(Σpart2+b3) + relu(Σpart3+b4) ----
__global__ void final_reduce_kernel(const float* __restrict__ b3,
                                    const float* __restrict__ b4,
                                    float* __restrict__ out) {
    int idx4 = blockIdx.x * blockDim.x + threadIdx.x;        // over (BB*HOUT)/4
    if (idx4 >= BB * HOUT / 4) return;
    int idx = idx4 * 4;
    int n   = idx % HOUT;

    float4 sg = *(const float4*)(part2 + idx);
    #pragma unroll
    for (int z = 1; z < S2; z++) {
        float4 v = *(const float4*)(part2 + (size_t)z * BB * HOUT + idx);
        sg.x += v.x; sg.y += v.y; sg.z += v.z; sg.w += v.w;
    }
    float4 sl = *(const float4*)(part3 + idx);
    #pragma unroll
    for (int z = 1; z < S3; z++) {
        float4 v = *(const float4*)(part3 + (size_t)z * BB * HOUT + idx);
        sl.x += v.x; sl.y += v.y; sl.z += v.z; sl.w += v.w;
    }
    float4 g3 = *(const float4*)(b3 + n);
    float4 g4 = *(const float4*)(b4 + n);
    float4 o;
    o.x = fmaxf(sg.x + g3.x, 0.0f) + fmaxf(sl.x + g4.x, 0.0f);
    o.y = fmaxf(sg.y + g3.y, 0.0f) + fmaxf(sl.y + g4.y, 0.0f);
    o.z = fmaxf(sg.z + g3.z, 0.0f) + fmaxf(sl.z + g4.z, 0.0f);
    o.w = fmaxf(sg.w + g3.w, 0.0f) + fmaxf(sl.w + g4.w, 0.0f);
    *(float4*)(out + idx) = o;        // relu(hg+hl) == relu(hg)+relu(hl) form
}

// ---------------- launch ----------------------------------------------------
extern "C" void kernel_launch(void* const* d_in, const int* in_sizes, int n_in,
                              void* d_out, int out_size) {
    const float* images    = (const float*)d_in[0];
    const float* locations = (const float*)d_in[1];
    const float* W1        = (const float*)d_in[2];
    const float* b1        = (const float*)d_in[3];
    const float* W2        = (const float*)d_in[4];
    const float* b2        = (const float*)d_in[5];
    const float* W3        = (const float*)d_in[6];
    const float* b3        = (const float*)d_in[7];
    const float* W4        = (const float*)d_in[8];
    const float* b4        = (const float*)d_in[9];
    float* out = (float*)d_out;
    (void)in_sizes; (void)n_in; (void)out_size;

    void *gp, *h1p, *h2p, *p1p, *p2p, *p3p;
    cudaGetSymbolAddress(&gp,  g_buf);
    cudaGetSymbolAddress(&h1p, h1_buf);
    cudaGetSymbolAddress(&h2p, h2_buf);
    cudaGetSymbolAddress(&p1p, part1);
    cudaGetSymbolAddress(&p2p, part2);
    cudaGetSymbolAddress(&p3p, part3);

    // 1) foveation -> g_buf
    foveate_kernel<<<(BB * GDIM + 255) / 256, 256>>>(images, locations);

    // 2) location FC -> h2_buf
    loc_fc_kernel<<<BB, HLN>>>(locations, W2, b2);

    // 3) hl partials: h2 @ W4   (256 x 1280, K=256, S=2) -> part3
    gemm_splitk_kernel<<<dim3(HOUT / 64, BB / 32, S3), 128>>>(
        (const float*)h2p, W4, (float*)p3p, BB, HOUT, HLN, HLN / S3);

    // 4) GEMM1 partials: g @ W1 (256 x 1024, K=9216, S=8) -> part1
    gemm_splitk_kernel<<<dim3(HGN / 64, BB / 32, S1), 128>>>(
        (const float*)gp, W1, (float*)p1p, BB, HGN, GDIM, GDIM / S1);

    // 5) h1 = relu(sum part1 + b1)
    reduce1_kernel<<<(BB * HGN / 4 + 255) / 256, 256>>>(b1);

    // 6) out partials: h1 @ W3  (256 x 1280, K=1024, S=4) -> part2
    gemm_splitk_kernel<<<dim3(HOUT / 64, BB / 32, S2), 128>>>(
        (const float*)h1p, W3, (float*)p2p, BB, HOUT, HGN, HGN / S2);

    // 7) out = relu(sum part2 + b3) + relu(sum part3 + b4)
    final_reduce_kernel<<<(BB * HOUT / 4 + 255) / 256, 256>>>(b3, b4, out);
}